// round 15
// baseline (speedup 1.0000x reference)
#include <cuda_runtime.h>
#include <cuda_bf16.h>

// ---------------------------------------------------------------------------
// GNN15: two GAT branches (int: 400K edges deg~4, nh: 1.6M edges deg~16)
// over 100K nodes, HEADS=3, FILT=16, then attention pooling to a scalar.
//
// R15: R14 + pool weight tables vectorized (float4 sA4/sD4, LDS.128) —
// pool's dominant cost was 72 scalar LDS/thread; now 24 LDS.128.
// ---------------------------------------------------------------------------

#define NN      100000
#define E_INT   400000
#define E_NH    1600000
#define VF      11
#define HEADS   3
#define HF      48
#define RS      64       // h/out row stride (floats) = 256B, 128B-aligned
#define XDIM    96
#define CAP0    32
#define CAP1    64
#define LOG2E   1.4426950408889634f

// ---------------- scratch (static device globals; no allocation) -----------
__device__ __align__(256) float g_h0[NN * RS];     // h[0..47] per row
__device__ __align__(256) float g_h1[NN * RS];
__device__ __align__(16) float4 g_es4_0[NN];       // es*log2e
__device__ __align__(16) float4 g_es4_1[NN];
__device__ __align__(16) float4 g_ed4_0[NN];       // ed*log2e
__device__ __align__(16) float4 g_ed4_1[NN];
__device__ __align__(256) float g_out0[NN * RS];   // NORMALIZED x rows
__device__ __align__(256) float g_out1[NN * RS];
__device__ int g_cnt0[NN];                          // zero-init; self-resetting
__device__ int g_cnt1[NN];
__device__ __align__(16) int4 g_ent0[NN * CAP0];    // (p0,p1,p2 bits, src)
__device__ __align__(16) int4 g_ent1[NN * CAP1];
__device__ float g_acc[8];                          // num[3], den[3]; self-reset
__device__ int   g_done;                            // pool last-block counter
__device__ int   g_is64[2];

__device__ __forceinline__ float ex2(float x) {
    float r;
    asm("ex2.approx.f32 %0, %1;" : "=f"(r) : "f"(x));
    return r;
}

// ---------------- node transform (+ edge dtype detect in block 0) ----------
// jax "int64" edges are int32 unless x64 is enabled. Values < 1e5 << 2^31,
// so if truly int64 every odd int32 word is 0. Check 16 of them.
__global__ void node_kernel(const float* __restrict__ feats,
                            const float* __restrict__ W0,
                            const float* __restrict__ as0, const float* __restrict__ ad0,
                            const float* __restrict__ W1,
                            const float* __restrict__ as1, const float* __restrict__ ad1,
                            const void* e0, const void* e1) {
    __shared__ float sW[2][VF * HF];
    __shared__ float sAs[2][HF];
    __shared__ float sAd[2][HF];
    int tid = threadIdx.x;
    if (blockIdx.x == 0 && tid == 0) {
        const int* a = (const int*)e0;
        const int* b = (const int*)e1;
        int is64a = 1, is64b = 1;
        #pragma unroll
        for (int k = 0; k < 16; k++) {
            if (a[2 * k + 1] != 0) is64a = 0;
            if (b[2 * k + 1] != 0) is64b = 0;
        }
        g_is64[0] = is64a;
        g_is64[1] = is64b;
    }
    for (int i = tid; i < VF * HF; i += blockDim.x) { sW[0][i] = W0[i]; sW[1][i] = W1[i]; }
    for (int i = tid; i < HF; i += blockDim.x) {
        sAs[0][i] = as0[i]; sAd[0][i] = ad0[i];
        sAs[1][i] = as1[i]; sAd[1][i] = ad1[i];
    }
    __syncthreads();

    int n = blockIdx.x * blockDim.x + tid;
    if (n >= NN) return;

    float x[VF];
    #pragma unroll
    for (int k = 0; k < VF; k++) x[k] = feats[(size_t)n * VF + k];

    #pragma unroll
    for (int b = 0; b < 2; b++) {
        float4* hout = (float4*)((b == 0 ? g_h0 : g_h1) + (size_t)n * RS);
        float es[HEADS] = {0.f, 0.f, 0.f};
        float ed[HEADS] = {0.f, 0.f, 0.f};
        #pragma unroll
        for (int j4 = 0; j4 < HF / 4; j4++) {
            float4 v;
            float* vf = (float*)&v;
            #pragma unroll
            for (int c = 0; c < 4; c++) {
                int j = j4 * 4 + c;
                float s = 0.f;
                #pragma unroll
                for (int k = 0; k < VF; k++) s += x[k] * sW[b][k * HF + j];
                vf[c] = s;
                int hh = j >> 4;
                es[hh] += s * sAs[b][j];
                ed[hh] += s * sAd[b][j];
            }
            hout[j4] = v;                      // STG.128: 8x fewer store wf
        }
        // log2e folded in: lrelu is positively homogeneous, so
        // exp(lrelu(v)) = ex2(lrelu(v*log2e)) exactly.
        (b == 0 ? g_es4_0 : g_es4_1)[n] =
            make_float4(es[0] * LOG2E, es[1] * LOG2E, es[2] * LOG2E, 0.f);
        (b == 0 ? g_ed4_0 : g_ed4_1)[n] =
            make_float4(ed[0] * LOG2E, ed[1] * LOG2E, ed[2] * LOG2E, 0.f);
    }
}

// ---------------- fill: bucketed CSR build with precomputed p --------------
__device__ __forceinline__ void fill_one(int s, int d,
                                         const float4* __restrict__ es4,
                                         const float4* __restrict__ ed4,
                                         int* __restrict__ cnt,
                                         int4* __restrict__ ent, int cap) {
    float4 a = es4[s];
    float4 b = ed4[d];
    float v0 = a.x + b.x, v1 = a.y + b.y, v2 = a.z + b.z;
    v0 = v0 > 0.f ? v0 : 0.2f * v0;            // leaky_relu(0.2), log2-domain
    v1 = v1 > 0.f ? v1 : 0.2f * v1;
    v2 = v2 > 0.f ? v2 : 0.2f * v2;
    float p0 = ex2(v0), p1 = ex2(v1), p2 = ex2(v2);
    int pos = atomicAdd(&cnt[d], 1);
    if (pos < cap)
        ent[d * cap + pos] = make_int4(__float_as_int(p0), __float_as_int(p1),
                                       __float_as_int(p2), s);
}

__global__ void fill_kernel(const void* __restrict__ e0, const void* __restrict__ e1) {
    int t = blockIdx.x * blockDim.x + threadIdx.x;
    const int H0 = E_INT / 2, H1 = E_NH / 2;
    if (t < H0) {
        int s0, s1, d0, d1;
        if (g_is64[0]) {
            const longlong2* p = (const longlong2*)e0;
            longlong2 sv = p[t], dv = p[H0 + t];
            s0 = (int)sv.x; s1 = (int)sv.y; d0 = (int)dv.x; d1 = (int)dv.y;
        } else {
            const int2* p = (const int2*)e0;
            int2 sv = p[t], dv = p[H0 + t];
            s0 = sv.x; s1 = sv.y; d0 = dv.x; d1 = dv.y;
        }
        fill_one(s0, d0, g_es4_0, g_ed4_0, g_cnt0, g_ent0, CAP0);
        fill_one(s1, d1, g_es4_0, g_ed4_0, g_cnt0, g_ent0, CAP0);
    } else if (t < H0 + H1) {
        int u = t - H0;
        int s0, s1, d0, d1;
        if (g_is64[1]) {
            const longlong2* p = (const longlong2*)e1;
            longlong2 sv = p[u], dv = p[H1 + u];
            s0 = (int)sv.x; s1 = (int)sv.y; d0 = (int)dv.x; d1 = (int)dv.y;
        } else {
            const int2* p = (const int2*)e1;
            int2 sv = p[u], dv = p[H1 + u];
            s0 = sv.x; s1 = sv.y; d0 = dv.x; d1 = dv.y;
        }
        fill_one(s0, d0, g_es4_1, g_ed4_1, g_cnt1, g_ent1, CAP1);
        fill_one(s1, d1, g_es4_1, g_ed4_1, g_cnt1, g_ent1, CAP1);
    }
}

// ---------------- consume: octet per dst row, normalized output ------------
__device__ __forceinline__ void edge_acc(int4 E, float4 hA, float4 hB, int sub,
                                         float4& acc0, float4& acc1,
                                         float& d0, float& d1, float& d2) {
    float p0 = __int_as_float(E.x);
    float p1 = __int_as_float(E.y);
    float p2 = __int_as_float(E.z);
    float pa = sub < 4 ? p0 : p1;
    acc0.x += pa * hA.x; acc0.y += pa * hA.y;
    acc0.z += pa * hA.z; acc0.w += pa * hA.w;
    acc1.x += p2 * hB.x; acc1.y += p2 * hB.y;   // lanes 4-7: duplicate result
    acc1.z += p2 * hB.z; acc1.w += p2 * hB.w;
    d0 += p0; d1 += p1; d2 += p2;
}

__global__ void __launch_bounds__(256, 4) consume_kernel() {
    int t = blockIdx.x * blockDim.x + threadIdx.x;
    int oc = t >> 3, sub = t & 7;
    if (oc >= 2 * NN) return;

    const float* h;
    const int4* ent;
    float* orow;
    int* cntp;
    int cap;
    if (oc < NN) {
        int r = oc;
        h = g_h0; ent = g_ent0 + (size_t)r * CAP0;
        orow = g_out0 + (size_t)r * RS;
        cntp = &g_cnt0[r]; cap = CAP0;
    } else {
        int r = oc - NN;
        h = g_h1; ent = g_ent1 + (size_t)r * CAP1;
        orow = g_out1 + (size_t)r * RS;
        cntp = &g_cnt1[r]; cap = CAP1;
    }
    int deg = *cntp;
    deg = deg < cap ? deg : cap;
    int subm = 8 + (sub & 3);            // head2 slots 8..11 (lanes 4-7 dup)

    float4 acc0 = make_float4(0.f, 0.f, 0.f, 0.f);
    float4 acc1 = make_float4(0.f, 0.f, 0.f, 0.f);
    float d0 = 0.f, d1 = 0.f, d2 = 0.f;

    int i = 0;
    for (; i + 4 <= deg; i += 4) {
        int4 E0 = ent[i], E1 = ent[i + 1], E2 = ent[i + 2], E3 = ent[i + 3];
        const float4* r0 = (const float4*)(h + (size_t)E0.w * RS);
        const float4* r1 = (const float4*)(h + (size_t)E1.w * RS);
        const float4* r2 = (const float4*)(h + (size_t)E2.w * RS);
        const float4* r3 = (const float4*)(h + (size_t)E3.w * RS);
        float4 A0 = r0[sub], B0 = r0[subm];
        float4 A1 = r1[sub], B1 = r1[subm];
        float4 A2 = r2[sub], B2 = r2[subm];
        float4 A3 = r3[sub], B3 = r3[subm];
        edge_acc(E0, A0, B0, sub, acc0, acc1, d0, d1, d2);
        edge_acc(E1, A1, B1, sub, acc0, acc1, d0, d1, d2);
        edge_acc(E2, A2, B2, sub, acc0, acc1, d0, d1, d2);
        edge_acc(E3, A3, B3, sub, acc0, acc1, d0, d1, d2);
    }
    for (; i < deg; i++) {
        int4 E = ent[i];
        const float4* hr = (const float4*)(h + (size_t)E.w * RS);
        float4 hA = hr[sub];
        float4 hB = hr[subm];
        edge_acc(E, hA, hB, sub, acc0, acc1, d0, d1, d2);
    }

    // normalize in-register (every lane holds the full den sums)
    float inv0 = 1.f / (d0 + 1e-16f);
    float inv1 = 1.f / (d1 + 1e-16f);
    float inv2 = 1.f / (d2 + 1e-16f);
    float invA = (sub < 4) ? inv0 : inv1;

    float4* or4 = (float4*)orow;
    or4[sub] = make_float4(acc0.x * invA, acc0.y * invA,
                           acc0.z * invA, acc0.w * invA);
    if (sub < 4)
        or4[8 + sub] = make_float4(acc1.x * inv2, acc1.y * inv2,
                                   acc1.z * inv2, acc1.w * inv2);
    if (sub == 5) *cntp = 0;             // reset for next replay
}

// ---------------- pooling: octet-per-row + fused finalize ------------------
// out = sum_h ( sum_n e^{tanh(x_n . attw_h)} * (x_n . dw_h) )
//             / ( sum_n e^{tanh(x_n . attw_h)} )  + b
__global__ void __launch_bounds__(256) pool_kernel(
        const float* __restrict__ attw, const float* __restrict__ dw,
        const float* __restrict__ bias, float* __restrict__ out) {
    __shared__ float4 sA4[XDIM];         // (attw[g][0..2], 0)  per dim g
    __shared__ float4 sD4[XDIM];         // (dw[0][g], dw[1][g], dw[2][g], 0)
    __shared__ float sAcc[6];
    int tid = threadIdx.x;
    if (tid < XDIM) {
        sA4[tid] = make_float4(attw[tid * HEADS + 0], attw[tid * HEADS + 1],
                               attw[tid * HEADS + 2], 0.f);
        sD4[tid] = make_float4(dw[0 * XDIM + tid], dw[1 * XDIM + tid],
                               dw[2 * XDIM + tid], 0.f);
    }
    if (tid < 6) sAcc[tid] = 0.f;
    __syncthreads();

    int t = blockIdx.x * blockDim.x + tid;
    int n = t >> 3, sub = t & 7;

    float sh[HEADS] = {0.f, 0.f, 0.f};
    float dh[HEADS] = {0.f, 0.f, 0.f};
    if (n < NN) {
        #pragma unroll
        for (int b = 0; b < 2; b++) {
            const float4* x = (const float4*)((b ? g_out1 : g_out0) + (size_t)n * RS);
            float4 v1 = x[sub];                                      // slots 0..7
            int base = b * HF;
            float q[4] = {v1.x, v1.y, v1.z, v1.w};
            #pragma unroll
            for (int c = 0; c < 4; c++) {
                int g = base + 4 * sub + c;
                float4 wa = sA4[g];
                float4 wd = sD4[g];
                sh[0] += q[c] * wa.x; sh[1] += q[c] * wa.y; sh[2] += q[c] * wa.z;
                dh[0] += q[c] * wd.x; dh[1] += q[c] * wd.y; dh[2] += q[c] * wd.z;
            }
            if (sub < 4) {                                           // slots 8..11
                float4 v2 = x[8 + sub];
                float q2[4] = {v2.x, v2.y, v2.z, v2.w};
                #pragma unroll
                for (int c = 0; c < 4; c++) {
                    int g = base + 32 + 4 * sub + c;
                    float4 wa = sA4[g];
                    float4 wd = sD4[g];
                    sh[0] += q2[c] * wa.x; sh[1] += q2[c] * wa.y; sh[2] += q2[c] * wa.z;
                    dh[0] += q2[c] * wd.x; dh[1] += q2[c] * wd.y; dh[2] += q2[c] * wd.z;
                }
            }
        }
    }
    // octet reduce (width 8) -> octet lane 0 has this node's sh/dh
    #pragma unroll
    for (int off = 4; off > 0; off >>= 1) {
        #pragma unroll
        for (int h = 0; h < HEADS; h++) {
            sh[h] += __shfl_down_sync(0xFFFFFFFFu, sh[h], off, 8);
            dh[h] += __shfl_down_sync(0xFFFFFFFFu, dh[h], off, 8);
        }
    }
    float num[HEADS] = {0.f, 0.f, 0.f};
    float den[HEADS] = {0.f, 0.f, 0.f};
    if (sub == 0 && n < NN) {
        #pragma unroll
        for (int h = 0; h < HEADS; h++) {
            float w = __expf(tanhf(sh[h]));
            num[h] = w * dh[h];
            den[h] = w;
        }
    }
    // cross-octet reduce (valid values at lanes 0,8,16,24; others zero)
    #pragma unroll
    for (int h = 0; h < HEADS; h++) {
        num[h] += __shfl_down_sync(0xFFFFFFFFu, num[h], 16);
        den[h] += __shfl_down_sync(0xFFFFFFFFu, den[h], 16);
        num[h] += __shfl_down_sync(0xFFFFFFFFu, num[h], 8);
        den[h] += __shfl_down_sync(0xFFFFFFFFu, den[h], 8);
    }
    if ((tid & 31) == 0) {
        #pragma unroll
        for (int h = 0; h < HEADS; h++) {
            atomicAdd(&sAcc[h], num[h]);
            atomicAdd(&sAcc[HEADS + h], den[h]);
        }
    }
    __syncthreads();
    if (tid < 6) atomicAdd(&g_acc[tid], sAcc[tid]);
    __threadfence();
    __syncthreads();
    if (tid == 0) {
        int done = atomicAdd(&g_done, 1);
        if (done == (int)gridDim.x - 1) {          // last block finalizes
            __threadfence();
            float r = 0.f;
            #pragma unroll
            for (int h = 0; h < HEADS; h++) r += g_acc[h] / g_acc[HEADS + h];
            out[0] = r + bias[0];
            #pragma unroll
            for (int k = 0; k < 6; k++) g_acc[k] = 0.f;   // reset for replay
            g_done = 0;
        }
    }
}

// ---------------------------------------------------------------------------
extern "C" void kernel_launch(void* const* d_in, const int* in_sizes, int n_in,
                              void* d_out, int out_size) {
    const float* node_feats = (const float*)d_in[0];
    const float* W_int   = (const float*)d_in[1];
    const float* asrc_i  = (const float*)d_in[2];
    const float* adst_i  = (const float*)d_in[3];
    const float* W_nh    = (const float*)d_in[4];
    const float* asrc_n  = (const float*)d_in[5];
    const float* adst_n  = (const float*)d_in[6];
    const float* att_w   = (const float*)d_in[7];
    const float* dense_w = (const float*)d_in[8];
    const float* dense_b = (const float*)d_in[9];
    const void*  edge_i  = d_in[10];
    const void*  edge_n  = d_in[11];
    float* out = (float*)d_out;

    node_kernel<<<(NN + 255) / 256, 256>>>(node_feats, W_int, asrc_i, adst_i,
                                           W_nh, asrc_n, adst_n, edge_i, edge_n);
    fill_kernel<<<((E_INT + E_NH) / 2 + 255) / 256, 256>>>(edge_i, edge_n);
    consume_kernel<<<(2 * NN * 8 + 255) / 256, 256>>>();
    pool_kernel<<<(NN * 8 + 255) / 256, 256>>>(att_w, dense_w, dense_b, out);
}

// round 16
// speedup vs baseline: 1.1428x; 1.1428x over previous
#include <cuda_runtime.h>
#include <cuda_bf16.h>

// ---------------------------------------------------------------------------
// GNN15: two GAT branches (int: 400K edges deg~4, nh: 1.6M edges deg~16)
// over 100K nodes, HEADS=3, FILT=16, then attention pooling to a scalar.
//
// R16: R14 architecture with R8's edge-weight scheme:
//  - es (log2e-scaled) embedded at h-row slot 12 -> consume's lanes 4-7 fetch
//    it with the SAME load as their B slot (no extra wavefront)
//  - fill shrinks to a 4B src scatter (was 16B entry + 2 scattered gathers)
//  - consume computes p in-loop (shuffle es, lrelu, ex2), normalizes
//    in-register, stores normalized x rows
//  - pool = R14 scalar version (the float4-LDS variant regressed)
// ---------------------------------------------------------------------------

#define NN      100000
#define E_INT   400000
#define E_NH    1600000
#define VF      11
#define HEADS   3
#define HF      48
#define RS      64       // h/out row stride (floats) = 256B, 128B-aligned
#define XDIM    96
#define CAP0    32
#define CAP1    64
#define LOG2E   1.4426950408889634f

// ---------------- scratch (static device globals; no allocation) -----------
__device__ __align__(256) float g_h0[NN * RS];     // h[0..47], es*log2e @ slot12
__device__ __align__(256) float g_h1[NN * RS];
__device__ __align__(16) float4 g_ed4_0[NN];       // ed*log2e
__device__ __align__(16) float4 g_ed4_1[NN];
__device__ __align__(256) float g_out0[NN * RS];   // NORMALIZED x rows
__device__ __align__(256) float g_out1[NN * RS];
__device__ int g_cnt0[NN];                          // zero-init; self-resetting
__device__ int g_cnt1[NN];
__device__ __align__(16) int g_srcs0[NN * CAP0];
__device__ __align__(16) int g_srcs1[NN * CAP1];
__device__ float g_acc[8];                          // num[3], den[3]; self-reset
__device__ int   g_done;                            // pool last-block counter
__device__ int   g_is64[2];

__device__ __forceinline__ float ex2(float x) {
    float r;
    asm("ex2.approx.f32 %0, %1;" : "=f"(r) : "f"(x));
    return r;
}

// ---------------- node transform (+ edge dtype detect in block 0) ----------
// jax "int64" edges are int32 unless x64 is enabled. Values < 1e5 << 2^31,
// so if truly int64 every odd int32 word is 0. Check 16 of them.
__global__ void node_kernel(const float* __restrict__ feats,
                            const float* __restrict__ W0,
                            const float* __restrict__ as0, const float* __restrict__ ad0,
                            const float* __restrict__ W1,
                            const float* __restrict__ as1, const float* __restrict__ ad1,
                            const void* e0, const void* e1) {
    __shared__ float sW[2][VF * HF];
    __shared__ float sAs[2][HF];
    __shared__ float sAd[2][HF];
    int tid = threadIdx.x;
    if (blockIdx.x == 0 && tid == 0) {
        const int* a = (const int*)e0;
        const int* b = (const int*)e1;
        int is64a = 1, is64b = 1;
        #pragma unroll
        for (int k = 0; k < 16; k++) {
            if (a[2 * k + 1] != 0) is64a = 0;
            if (b[2 * k + 1] != 0) is64b = 0;
        }
        g_is64[0] = is64a;
        g_is64[1] = is64b;
    }
    for (int i = tid; i < VF * HF; i += blockDim.x) { sW[0][i] = W0[i]; sW[1][i] = W1[i]; }
    for (int i = tid; i < HF; i += blockDim.x) {
        sAs[0][i] = as0[i]; sAd[0][i] = ad0[i];
        sAs[1][i] = as1[i]; sAd[1][i] = ad1[i];
    }
    __syncthreads();

    int n = blockIdx.x * blockDim.x + tid;
    if (n >= NN) return;

    float x[VF];
    #pragma unroll
    for (int k = 0; k < VF; k++) x[k] = feats[(size_t)n * VF + k];

    #pragma unroll
    for (int b = 0; b < 2; b++) {
        float4* hout = (float4*)((b == 0 ? g_h0 : g_h1) + (size_t)n * RS);
        float es[HEADS] = {0.f, 0.f, 0.f};
        float ed[HEADS] = {0.f, 0.f, 0.f};
        #pragma unroll
        for (int j4 = 0; j4 < HF / 4; j4++) {
            float4 v;
            float* vf = (float*)&v;
            #pragma unroll
            for (int c = 0; c < 4; c++) {
                int j = j4 * 4 + c;
                float s = 0.f;
                #pragma unroll
                for (int k = 0; k < VF; k++) s += x[k] * sW[b][k * HF + j];
                vf[c] = s;
                int hh = j >> 4;
                es[hh] += s * sAs[b][j];
                ed[hh] += s * sAd[b][j];
            }
            hout[j4] = v;                      // STG.128
        }
        // log2e folded in: lrelu is positively homogeneous, so
        // exp(lrelu(v)) = ex2(lrelu(v*log2e)) exactly.  es lives @ slot 12.
        hout[12] = make_float4(es[0] * LOG2E, es[1] * LOG2E, es[2] * LOG2E, 0.f);
        (b == 0 ? g_ed4_0 : g_ed4_1)[n] =
            make_float4(ed[0] * LOG2E, ed[1] * LOG2E, ed[2] * LOG2E, 0.f);
    }
}

// ---------------- fill: minimal bucketed CSR build (src only, 4B) ----------
__global__ void fill_kernel(const void* __restrict__ e0, const void* __restrict__ e1) {
    int t = blockIdx.x * blockDim.x + threadIdx.x;
    const int H0 = E_INT / 2, H1 = E_NH / 2;
    if (t < H0) {
        int s0, s1, d0, d1;
        if (g_is64[0]) {
            const longlong2* p = (const longlong2*)e0;
            longlong2 sv = p[t], dv = p[H0 + t];
            s0 = (int)sv.x; s1 = (int)sv.y; d0 = (int)dv.x; d1 = (int)dv.y;
        } else {
            const int2* p = (const int2*)e0;
            int2 sv = p[t], dv = p[H0 + t];
            s0 = sv.x; s1 = sv.y; d0 = dv.x; d1 = dv.y;
        }
        int p0 = atomicAdd(&g_cnt0[d0], 1);
        if (p0 < CAP0) g_srcs0[d0 * CAP0 + p0] = s0;
        int p1 = atomicAdd(&g_cnt0[d1], 1);
        if (p1 < CAP0) g_srcs0[d1 * CAP0 + p1] = s1;
    } else if (t < H0 + H1) {
        int u = t - H0;
        int s0, s1, d0, d1;
        if (g_is64[1]) {
            const longlong2* p = (const longlong2*)e1;
            longlong2 sv = p[u], dv = p[H1 + u];
            s0 = (int)sv.x; s1 = (int)sv.y; d0 = (int)dv.x; d1 = (int)dv.y;
        } else {
            const int2* p = (const int2*)e1;
            int2 sv = p[u], dv = p[H1 + u];
            s0 = sv.x; s1 = sv.y; d0 = dv.x; d1 = dv.y;
        }
        int p0 = atomicAdd(&g_cnt1[d0], 1);
        if (p0 < CAP1) g_srcs1[d0 * CAP1 + p0] = s0;
        int p1 = atomicAdd(&g_cnt1[d1], 1);
        if (p1 < CAP1) g_srcs1[d1 * CAP1 + p1] = s1;
    }
}

// ---------------- consume: octet per dst row, p in-loop, normalized out ----
__device__ __forceinline__ void edge_acc(float4 hA, float4 hB, float4 ed,
                                         unsigned octmask, int sub,
                                         float4& acc0, float4& acc1,
                                         float& d0, float& d1, float& d2) {
    float esx = __shfl_sync(octmask, hB.x, 4, 8);    // lane base+4 holds es
    float esy = __shfl_sync(octmask, hB.y, 4, 8);
    float esz = __shfl_sync(octmask, hB.z, 4, 8);
    float v0 = esx + ed.x, v1 = esy + ed.y, v2 = esz + ed.z;
    v0 = v0 > 0.f ? v0 : 0.2f * v0;        // leaky_relu(0.2), log2-domain
    v1 = v1 > 0.f ? v1 : 0.2f * v1;
    v2 = v2 > 0.f ? v2 : 0.2f * v2;
    float p0 = ex2(v0);                    // = exp(lrelu(raw)), exact commute
    float p1 = ex2(v1);
    float p2 = ex2(v2);
    float pa = sub < 4 ? p0 : p1;
    acc0.x += pa * hA.x; acc0.y += pa * hA.y;
    acc0.z += pa * hA.z; acc0.w += pa * hA.w;
    if (sub < 4) {
        acc1.x += p2 * hB.x; acc1.y += p2 * hB.y;
        acc1.z += p2 * hB.z; acc1.w += p2 * hB.w;
    }
    d0 += p0; d1 += p1; d2 += p2;
}

__global__ void __launch_bounds__(256, 4) consume_kernel() {
    int t = blockIdx.x * blockDim.x + threadIdx.x;
    int oc = t >> 3, sub = t & 7;
    if (oc >= 2 * NN) return;

    const float* h;
    const int* srcs;
    float4 ed;
    float* orow;
    int* cntp;
    int cap;
    if (oc < NN) {
        int r = oc;
        h = g_h0; srcs = g_srcs0 + (size_t)r * CAP0;
        ed = g_ed4_0[r]; orow = g_out0 + (size_t)r * RS;
        cntp = &g_cnt0[r]; cap = CAP0;
    } else {
        int r = oc - NN;
        h = g_h1; srcs = g_srcs1 + (size_t)r * CAP1;
        ed = g_ed4_1[r]; orow = g_out1 + (size_t)r * RS;
        cntp = &g_cnt1[r]; cap = CAP1;
    }
    int deg = *cntp;
    deg = deg < cap ? deg : cap;

    int subB = sub < 4 ? 8 + sub : 12;     // lanes 0-3: head2 slots; 4-7: es
    unsigned octmask = 0xFFu << (threadIdx.x & 24);

    float4 acc0 = make_float4(0.f, 0.f, 0.f, 0.f);
    float4 acc1 = make_float4(0.f, 0.f, 0.f, 0.f);
    float d0 = 0.f, d1 = 0.f, d2 = 0.f;

    int i = 0;
    for (; i + 4 <= deg; i += 4) {
        int4 s4 = *(const int4*)(srcs + i);            // 16B-aligned bucket
        const float4* r0 = (const float4*)(h + (size_t)s4.x * RS);
        const float4* r1 = (const float4*)(h + (size_t)s4.y * RS);
        const float4* r2 = (const float4*)(h + (size_t)s4.z * RS);
        const float4* r3 = (const float4*)(h + (size_t)s4.w * RS);
        // issue all 8 gathers before consuming any (MLP ~8/thread)
        float4 A0 = r0[sub], B0 = r0[subB];
        float4 A1 = r1[sub], B1 = r1[subB];
        float4 A2 = r2[sub], B2 = r2[subB];
        float4 A3 = r3[sub], B3 = r3[subB];
        edge_acc(A0, B0, ed, octmask, sub, acc0, acc1, d0, d1, d2);
        edge_acc(A1, B1, ed, octmask, sub, acc0, acc1, d0, d1, d2);
        edge_acc(A2, B2, ed, octmask, sub, acc0, acc1, d0, d1, d2);
        edge_acc(A3, B3, ed, octmask, sub, acc0, acc1, d0, d1, d2);
    }
    for (; i < deg; i++) {
        int s = srcs[i];
        const float4* hr = (const float4*)(h + (size_t)s * RS);
        float4 hA = hr[sub];
        float4 hB = hr[subB];
        edge_acc(hA, hB, ed, octmask, sub, acc0, acc1, d0, d1, d2);
    }

    // normalize in-register (every lane holds the full den sums)
    float inv0 = 1.f / (d0 + 1e-16f);
    float inv1 = 1.f / (d1 + 1e-16f);
    float inv2 = 1.f / (d2 + 1e-16f);
    float invA = (sub < 4) ? inv0 : inv1;

    float4* or4 = (float4*)orow;
    or4[sub] = make_float4(acc0.x * invA, acc0.y * invA,
                           acc0.z * invA, acc0.w * invA);
    if (sub < 4)
        or4[8 + sub] = make_float4(acc1.x * inv2, acc1.y * inv2,
                                   acc1.z * inv2, acc1.w * inv2);
    if (sub == 5) *cntp = 0;             // reset for next replay
}

// ---------------- pooling: octet-per-row + fused finalize (R14 scalar) -----
// out = sum_h ( sum_n e^{tanh(x_n . attw_h)} * (x_n . dw_h) )
//             / ( sum_n e^{tanh(x_n . attw_h)} )  + b
__global__ void __launch_bounds__(256) pool_kernel(
        const float* __restrict__ attw, const float* __restrict__ dw,
        const float* __restrict__ bias, float* __restrict__ out) {
    __shared__ float sA[XDIM * HEADS];   // attw: [96,3] row-major
    __shared__ float sD[XDIM * HEADS];   // dense_w: [288] = [3][96] h-major
    __shared__ float sAcc[6];
    int tid = threadIdx.x;
    for (int i = tid; i < XDIM * HEADS; i += blockDim.x) { sA[i] = attw[i]; sD[i] = dw[i]; }
    if (tid < 6) sAcc[tid] = 0.f;
    __syncthreads();

    int t = blockIdx.x * blockDim.x + tid;
    int n = t >> 3, sub = t & 7;

    float sh[HEADS] = {0.f, 0.f, 0.f};
    float dh[HEADS] = {0.f, 0.f, 0.f};
    if (n < NN) {
        #pragma unroll
        for (int b = 0; b < 2; b++) {
            const float4* x = (const float4*)((b ? g_out1 : g_out0) + (size_t)n * RS);
            float4 v1 = x[sub];                                      // slots 0..7
            int base = b * HF;
            float q[4] = {v1.x, v1.y, v1.z, v1.w};
            #pragma unroll
            for (int c = 0; c < 4; c++) {
                int g = base + 4 * sub + c;
                #pragma unroll
                for (int h = 0; h < HEADS; h++) {
                    sh[h] += q[c] * sA[g * HEADS + h];
                    dh[h] += q[c] * sD[h * XDIM + g];
                }
            }
            if (sub < 4) {                                           // slots 8..11
                float4 v2 = x[8 + sub];
                float q2[4] = {v2.x, v2.y, v2.z, v2.w};
                #pragma unroll
                for (int c = 0; c < 4; c++) {
                    int g = base + 32 + 4 * sub + c;
                    #pragma unroll
                    for (int h = 0; h < HEADS; h++) {
                        sh[h] += q2[c] * sA[g * HEADS + h];
                        dh[h] += q2[c] * sD[h * XDIM + g];
                    }
                }
            }
        }
    }
    // octet reduce (width 8) -> octet lane 0 has this node's sh/dh
    #pragma unroll
    for (int off = 4; off > 0; off >>= 1) {
        #pragma unroll
        for (int h = 0; h < HEADS; h++) {
            sh[h] += __shfl_down_sync(0xFFFFFFFFu, sh[h], off, 8);
            dh[h] += __shfl_down_sync(0xFFFFFFFFu, dh[h], off, 8);
        }
    }
    float num[HEADS] = {0.f, 0.f, 0.f};
    float den[HEADS] = {0.f, 0.f, 0.f};
    if (sub == 0 && n < NN) {
        #pragma unroll
        for (int h = 0; h < HEADS; h++) {
            float w = __expf(tanhf(sh[h]));
            num[h] = w * dh[h];
            den[h] = w;
        }
    }
    // cross-octet reduce (valid values at lanes 0,8,16,24; others zero)
    #pragma unroll
    for (int h = 0; h < HEADS; h++) {
        num[h] += __shfl_down_sync(0xFFFFFFFFu, num[h], 16);
        den[h] += __shfl_down_sync(0xFFFFFFFFu, den[h], 16);
        num[h] += __shfl_down_sync(0xFFFFFFFFu, num[h], 8);
        den[h] += __shfl_down_sync(0xFFFFFFFFu, den[h], 8);
    }
    if ((tid & 31) == 0) {
        #pragma unroll
        for (int h = 0; h < HEADS; h++) {
            atomicAdd(&sAcc[h], num[h]);
            atomicAdd(&sAcc[HEADS + h], den[h]);
        }
    }
    __syncthreads();
    if (tid < 6) atomicAdd(&g_acc[tid], sAcc[tid]);
    __threadfence();
    __syncthreads();
    if (tid == 0) {
        int done = atomicAdd(&g_done, 1);
        if (done == (int)gridDim.x - 1) {          // last block finalizes
            __threadfence();
            float r = 0.f;
            #pragma unroll
            for (int h = 0; h < HEADS; h++) r += g_acc[h] / g_acc[HEADS + h];
            out[0] = r + bias[0];
            #pragma unroll
            for (int k = 0; k < 6; k++) g_acc[k] = 0.f;   // reset for replay
            g_done = 0;
        }
    }
}

// ---------------------------------------------------------------------------
extern "C" void kernel_launch(void* const* d_in, const int* in_sizes, int n_in,
                              void* d_out, int out_size) {
    const float* node_feats = (const float*)d_in[0];
    const float* W_int   = (const float*)d_in[1];
    const float* asrc_i  = (const float*)d_in[2];
    const float* adst_i  = (const float*)d_in[3];
    const float* W_nh    = (const float*)d_in[4];
    const float* asrc_n  = (const float*)d_in[5];
    const float* adst_n  = (const float*)d_in[6];
    const float* att_w   = (const float*)d_in[7];
    const float* dense_w = (const float*)d_in[8];
    const float* dense_b = (const float*)d_in[9];
    const void*  edge_i  = d_in[10];
    const void*  edge_n  = d_in[11];
    float* out = (float*)d_out;

    node_kernel<<<(NN + 255) / 256, 256>>>(node_feats, W_int, asrc_i, adst_i,
                                           W_nh, asrc_n, adst_n, edge_i, edge_n);
    fill_kernel<<<((E_INT + E_NH) / 2 + 255) / 256, 256>>>(edge_i, edge_n);
    consume_kernel<<<(2 * NN * 8 + 255) / 256, 256>>>();
    pool_kernel<<<(NN * 8 + 255) / 256, 256>>>(att_w, dense_w, dense_b, out);
}